// round 5
// baseline (speedup 1.0000x reference)
#include <cuda_runtime.h>
#include <math.h>

#define NUM_WIRES 18
#define BATCH     64
#define DIM       262144            // 2^18
#define CHUNK_BITS 13
#define CHUNK     8192              // 2^13
#define NCHUNK    32                // 2^(18-13)
#define PL_THREADS 512
#define PH_THREADS 256

// Ping-pong state buffers. __device__ globals are the sanctioned scratch.
__device__ float2 g_buf0[BATCH * DIM];
__device__ float2 g_buf1[BATCH * DIM];
// Expval partials: [batch][chunk][wire]
__device__ float g_partial[BATCH * NCHUNK * NUM_WIRES];

// ---------------------------------------------------------------------------
// helpers
// ---------------------------------------------------------------------------

// Apply fused RZ(tz)*RY(ty) to amplitude pair (a = bit0 branch, b = bit1 branch)
__device__ __forceinline__ void apply_gate(float2& a, float2& b, float4 g) {
    float ar = fmaf(g.x, a.x, -g.y * b.x);
    float ai = fmaf(g.x, a.y, -g.y * b.y);
    float br = fmaf(g.y, a.x,  g.x * b.x);
    float bi = fmaf(g.y, a.y,  g.x * b.y);
    a.x = fmaf(g.z, ar,  g.w * ai);
    a.y = fmaf(g.z, ai, -g.w * ar);
    b.x = fmaf(g.z, br, -g.w * bi);
    b.y = fmaf(g.z, bi,  g.w * br);
}

// smem XOR swizzle on float2 index; conflict-free per half-warp for all stage
// patterns used below (verified per-stage).
__device__ __forceinline__ int SW(int t) { return t ^ ((t >> 4) & 63); }

// inverse Gray code (prefix-xor from MSB), valid for values < 2^16
__device__ __forceinline__ int invgray(int t) {
    t ^= t >> 1; t ^= t >> 2; t ^= t >> 4; t ^= t >> 8;
    return t;
}

// gate coefficients for wires [w0, w0+n) of a layer into shared memory
__device__ __forceinline__ void load_gates(float4* sg, const float* params,
                                           int layer, int w0, int n, int tid) {
    if (tid < n) {
        int w = w0 + tid;
        float ty = params[(layer * 2 + 0) * NUM_WIRES + w] * 0.5f;
        float tz = params[(layer * 2 + 1) * NUM_WIRES + w] * 0.5f;
        sg[tid] = make_float4(cosf(ty), sinf(ty), cosf(tz), sinf(tz));
    }
}

// ---------------------------------------------------------------------------
// pass_high: wires 0..4 (index bits 17..13). Register-only, in-place.
// 32 float2 per thread strided 2^13, loads batched (MLP=32), 128-reg budget.
// ---------------------------------------------------------------------------
__global__ void __launch_bounds__(PH_THREADS, 2)
k_pass_high(float2* __restrict__ buf, const float* __restrict__ params, int layer) {
    __shared__ float4 sg[5];
    load_gates(sg, params, layer, 0, 5, threadIdx.x);
    __syncthreads();

    int gid = blockIdx.x * PH_THREADS + threadIdx.x;   // BATCH*CHUNK threads
    int b = gid >> CHUNK_BITS;
    int u = gid & (CHUNK - 1);
    float2* p = buf + (long)b * DIM + u;

    float2 x[32];
#pragma unroll
    for (int r = 0; r < 32; ++r) x[r] = p[(long)r << CHUNK_BITS];

#pragma unroll
    for (int w = 0; w < 5; ++w) {
        float4 g = sg[w];
        int m = 16 >> w;                     // wire w <-> r-bit (4-w)
#pragma unroll
        for (int r = 0; r < 32; ++r)
            if (!(r & m)) apply_gate(x[r], x[r | m], g);
    }

#pragma unroll
    for (int r = 0; r < 32; ++r) p[(long)r << CHUNK_BITS] = x[r];
}

// first variant: reads separate re/im arrays, writes interleaved float2
__global__ void __launch_bounds__(PH_THREADS, 2)
k_pass_high_first(const float* __restrict__ sre,
                  const float* __restrict__ sim,
                  float2* __restrict__ out,
                  const float* __restrict__ params) {
    __shared__ float4 sg[5];
    load_gates(sg, params, 0, 0, 5, threadIdx.x);
    __syncthreads();

    int gid = blockIdx.x * PH_THREADS + threadIdx.x;
    int b = gid >> CHUNK_BITS;
    int u = gid & (CHUNK - 1);
    long base = (long)b * DIM + u;

    float2 x[32];
#pragma unroll
    for (int r = 0; r < 32; ++r) x[r].x = sre[base + ((long)r << CHUNK_BITS)];
#pragma unroll
    for (int r = 0; r < 32; ++r) x[r].y = sim[base + ((long)r << CHUNK_BITS)];

#pragma unroll
    for (int w = 0; w < 5; ++w) {
        float4 g = sg[w];
        int m = 16 >> w;
#pragma unroll
        for (int r = 0; r < 32; ++r)
            if (!(r & m)) apply_gate(x[r], x[r | m], g);
    }
    float2* p = out + base;
#pragma unroll
    for (int r = 0; r < 32; ++r) p[(long)r << CHUNK_BITS] = x[r];
}

// ---------------------------------------------------------------------------
// pass_low: wires 5..17 (bits 12..0) in 64KB shared tiles (2 CTAs/SM), then
// the CNOT-ladder permutation (inverse-Gray scatter, float4-pair stores).
// last==true: skip state write, compute <Z_w> partials instead.
// ---------------------------------------------------------------------------
__global__ void __launch_bounds__(PL_THREADS, 2)
k_pass_low(const float2* __restrict__ in,
           float2* __restrict__ out,
           const float* __restrict__ params,
           int layer, int last) {
    extern __shared__ float2 sh[];           // 2^13 float2 = 64KB
    __shared__ float4 sg[13];                // wires 5..17 -> sg[w-5]
    int tid = threadIdx.x;
    load_gates(sg, params, layer, 5, 13, tid);

    int b = blockIdx.x >> 5;
    int H = blockIdx.x & 31;                 // source chunk (bits 13..17)
    const float4* src4 = (const float4*)(in + (long)b * DIM + ((long)H << CHUNK_BITS));

    // batched fill: 8 independent 16B loads per thread, then smem stores
    {
        float4 v[8];
#pragma unroll
        for (int k = 0; k < 8; ++k) v[k] = src4[tid + k * PL_THREADS];
#pragma unroll
        for (int k = 0; k < 8; ++k) {
            int t = 2 * (tid + k * PL_THREADS);
            sh[SW(t)]     = make_float2(v[k].x, v[k].y);
            sh[SW(t + 1)] = make_float2(v[k].z, v[k].w);
        }
    }
    __syncthreads();

    // stage A: bits 0..3 (wires 17..14). 512 groups of 16, 1 per thread.
    {
        int base = tid << 4;
        float2 x[16];
#pragma unroll
        for (int j = 0; j < 16; ++j) x[j] = sh[SW(base + j)];
#pragma unroll
        for (int p = 0; p < 4; ++p) {
            float4 g = sg[12 - p];           // wire 17-p
            int m = 1 << p;
#pragma unroll
            for (int j = 0; j < 16; ++j)
                if (!(j & m)) apply_gate(x[j], x[j | m], g);
        }
#pragma unroll
        for (int j = 0; j < 16; ++j) sh[SW(base + j)] = x[j];
    }
    __syncthreads();

    // stage B: bits 4..7 (wires 13..10). group = bits 0..3 x bits 8..12.
    {
        int base = (tid & 15) | ((tid >> 4) << 8);
        float2 x[16];
#pragma unroll
        for (int j = 0; j < 16; ++j) x[j] = sh[SW(base | (j << 4))];
#pragma unroll
        for (int p = 0; p < 4; ++p) {
            float4 g = sg[8 - p];            // wire 13-p
            int m = 1 << p;
#pragma unroll
            for (int j = 0; j < 16; ++j)
                if (!(j & m)) apply_gate(x[j], x[j | m], g);
        }
#pragma unroll
        for (int j = 0; j < 16; ++j) sh[SW(base | (j << 4))] = x[j];
    }
    __syncthreads();

    // stage C: bits 8..11 (wires 9..6). group = bits 0..7 x bit 12.
    {
        int base = (tid & 255) | ((tid >> 8) << 12);
        float2 x[16];
#pragma unroll
        for (int j = 0; j < 16; ++j) x[j] = sh[SW(base | (j << 8))];
#pragma unroll
        for (int p = 0; p < 4; ++p) {
            float4 g = sg[4 - p];            // wire 9-p
            int m = 1 << p;
#pragma unroll
            for (int j = 0; j < 16; ++j)
                if (!(j & m)) apply_gate(x[j], x[j | m], g);
        }
#pragma unroll
        for (int j = 0; j < 16; ++j) sh[SW(base | (j << 8))] = x[j];
    }
    __syncthreads();

    // stage D: bit 12 (wire 5). 4096 pairs, 8 per thread.
    {
        float4 g = sg[0];                    // wire 5
#pragma unroll
        for (int j = 0; j < 8; ++j) {
            int lo = tid * 8 + j;
            float2 a = sh[SW(lo)];
            float2 bb = sh[SW(lo | 4096)];
            apply_gate(a, bb, g);
            sh[SW(lo)] = a;
            sh[SW(lo | 4096)] = bb;
        }
    }
    __syncthreads();

    // CNOT-ladder permutation: dest = invgray18(src)
    int pm = (__popc(H) & 1) ? (CHUNK - 1) : 0;
    int Hd = H ^ (H >> 1); Hd ^= Hd >> 2; Hd ^= Hd >> 4;  // invgray5

    if (!last) {
        // invgray maps pair {t,t+1} (t even) to {q, q^1}: 16B stores stay legal
        float4* dst4 = (float4*)(out + (long)b * DIM + ((long)Hd << CHUNK_BITS));
#pragma unroll
        for (int k = 0; k < 8; ++k) {
            int t = 2 * (tid + k * PL_THREADS);
            int q = invgray(t) ^ pm;
            float2 v0 = sh[SW(t)];
            float2 v1 = sh[SW(t + 1)];
            float4 o = (q & 1) ? make_float4(v1.x, v1.y, v0.x, v0.y)
                               : make_float4(v0.x, v0.y, v1.x, v1.y);
            dst4[q >> 1] = o;
        }
    } else {
        float acc[NUM_WIRES];
#pragma unroll
        for (int w = 0; w < NUM_WIRES; ++w) acc[w] = 0.0f;
        int hi = Hd << CHUNK_BITS;
#pragma unroll
        for (int k = 0; k < 8; ++k) {
            int t = 2 * (tid + k * PL_THREADS);
            float2 v0 = sh[SW(t)];
            float2 v1 = sh[SW(t + 1)];
            float pr0 = v0.x * v0.x + v0.y * v0.y;
            float pr1 = v1.x * v1.x + v1.y * v1.y;
            int q = invgray(t) ^ pm;
            int d = hi | q;
            float both = pr0 + pr1;
            unsigned bb = __float_as_uint(both);
#pragma unroll
            for (int w = 0; w < 17; ++w) {
                unsigned bit = (unsigned)(d >> (17 - w)) & 1u;
                acc[w] += __uint_as_float(bb ^ (bit << 31));
            }
            float diff = pr0 - pr1;
            acc[17] += (q & 1) ? -diff : diff;
        }
#pragma unroll
        for (int w = 0; w < NUM_WIRES; ++w)
#pragma unroll
            for (int o = 16; o; o >>= 1)
                acc[w] += __shfl_down_sync(0xFFFFFFFFu, acc[w], o);
        __syncthreads();
        float* scratch = (float*)sh;
        int warp = tid >> 5, lane = tid & 31;
        if (lane == 0)
#pragma unroll
            for (int w = 0; w < NUM_WIRES; ++w) scratch[warp * NUM_WIRES + w] = acc[w];
        __syncthreads();
        if (tid < NUM_WIRES) {
            float s = 0.0f;
#pragma unroll
            for (int k = 0; k < PL_THREADS / 32; ++k) s += scratch[k * NUM_WIRES + tid];
            g_partial[(b * NCHUNK + H) * NUM_WIRES + tid] = s;
        }
    }
}

// ---------------------------------------------------------------------------
// head: feats @ head_w.T + head_b
// ---------------------------------------------------------------------------
__global__ void k_head(const float* __restrict__ head_w,
                       const float* __restrict__ head_b,
                       float* __restrict__ out) {
    int b = threadIdx.x;
    if (b < BATCH) {
        float s = head_b[0];
#pragma unroll
        for (int w = 0; w < NUM_WIRES; ++w) {
            float f = 0.0f;
#pragma unroll
            for (int c = 0; c < NCHUNK; ++c)
                f += g_partial[(b * NCHUNK + c) * NUM_WIRES + w];
            s = fmaf(f, head_w[w], s);
        }
        out[b] = s;
    }
}

// ---------------------------------------------------------------------------
extern "C" void kernel_launch(void* const* d_in, const int* in_sizes, int n_in,
                              void* d_out, int out_size) {
    const float* state_re = (const float*)d_in[0];
    const float* state_im = (const float*)d_in[1];
    const float* params   = (const float*)d_in[2];
    const float* head_w   = (const float*)d_in[3];
    const float* head_b   = (const float*)d_in[4];
    float* out = (float*)d_out;

    cudaFuncSetAttribute(k_pass_low, cudaFuncAttributeMaxDynamicSharedMemorySize,
                         CHUNK * (int)sizeof(float2));

    const int ph_blocks = (BATCH * CHUNK) / PH_THREADS;   // 2048
    const int pl_blocks = BATCH * NCHUNK;                 // 2048
    const int shmem = CHUNK * (int)sizeof(float2);        // 64KB

    // layer 0
    k_pass_high_first<<<ph_blocks, PH_THREADS>>>(state_re, state_im, g_buf0, params);
    k_pass_low<<<pl_blocks, PL_THREADS, shmem>>>(g_buf0, g_buf1, params, 0, 0);
    // layer 1
    k_pass_high<<<ph_blocks, PH_THREADS>>>(g_buf1, params, 1);
    k_pass_low<<<pl_blocks, PL_THREADS, shmem>>>(g_buf1, g_buf0, params, 1, 0);
    // layer 2
    k_pass_high<<<ph_blocks, PH_THREADS>>>(g_buf0, params, 2);
    k_pass_low<<<pl_blocks, PL_THREADS, shmem>>>(g_buf0, g_buf1, params, 2, 1);

    k_head<<<1, 64>>>(head_w, head_b, out);
}

// round 6
// speedup vs baseline: 13.5567x; 13.5567x over previous
#include <cuda_runtime.h>
#include <cuda_fp16.h>
#include <math.h>

#define NUM_WIRES 18
#define BATCH     64
#define GB        32                // batch-group size (two groups: L2-resident)
#define DIM       262144            // 2^18
#define CHUNK_BITS 13
#define CHUNK     8192              // 2^13
#define NCHUNK    32                // 2^(18-13)
#define PL_THREADS 512
#define PH_THREADS 256

// Half-precision ping-pong state buffers (67MB each; both fit L2 together for
// a 32-element batch group). __device__ globals are the sanctioned scratch.
__device__ __half2 g_h0[BATCH * DIM];
__device__ __half2 g_h1[BATCH * DIM];
// Expval partials: [batch][chunk][wire]
__device__ float g_partial[BATCH * NCHUNK * NUM_WIRES];

// ---------------------------------------------------------------------------
// helpers
// ---------------------------------------------------------------------------

__device__ __forceinline__ void apply_gate(float2& a, float2& b, float4 g) {
    float ar = fmaf(g.x, a.x, -g.y * b.x);
    float ai = fmaf(g.x, a.y, -g.y * b.y);
    float br = fmaf(g.y, a.x,  g.x * b.x);
    float bi = fmaf(g.y, a.y,  g.x * b.y);
    a.x = fmaf(g.z, ar,  g.w * ai);
    a.y = fmaf(g.z, ai, -g.w * ar);
    b.x = fmaf(g.z, br, -g.w * bi);
    b.y = fmaf(g.z, bi,  g.w * br);
}

// smem XOR swizzle on float2 index (conflict-mitigating for all stage patterns)
__device__ __forceinline__ int SW(int t) { return t ^ ((t >> 4) & 63); }

// inverse Gray code (prefix-xor from MSB), valid for values < 2^16
__device__ __forceinline__ int invgray(int t) {
    t ^= t >> 1; t ^= t >> 2; t ^= t >> 4; t ^= t >> 8;
    return t;
}

__device__ __forceinline__ unsigned h2bits(__half2 h) {
    unsigned lo = __half_as_ushort(__low2half(h));
    unsigned hi = __half_as_ushort(__high2half(h));
    return lo | (hi << 16);
}
__device__ __forceinline__ float2 bits2f2(unsigned u) {
    __half2 h = __halves2half2(__ushort_as_half((unsigned short)(u & 0xFFFF)),
                               __ushort_as_half((unsigned short)(u >> 16)));
    return __half22float2(h);
}
__device__ __forceinline__ unsigned f22bits(float2 v) {
    return h2bits(__float22half2_rn(v));
}

// gate coefficients for wires [w0, w0+n) of a layer into shared memory
__device__ __forceinline__ void load_gates(float4* sg, const float* params,
                                           int layer, int w0, int n, int tid) {
    if (tid < n) {
        int w = w0 + tid;
        float ty = params[(layer * 2 + 0) * NUM_WIRES + w] * 0.5f;
        float tz = params[(layer * 2 + 1) * NUM_WIRES + w] * 0.5f;
        sg[tid] = make_float4(cosf(ty), sinf(ty), cosf(tz), sinf(tz));
    }
}

// ---------------------------------------------------------------------------
// pass_high: wires 0..4 (index bits 17..13). Register-only, in-place on half2.
// 32 amplitudes per thread strided 2^13; loads batched; fp32 compute.
// ---------------------------------------------------------------------------
__global__ void __launch_bounds__(PH_THREADS, 2)
k_pass_high(__half2* __restrict__ buf, const float* __restrict__ params, int layer) {
    __shared__ float4 sg[5];
    load_gates(sg, params, layer, 0, 5, threadIdx.x);
    __syncthreads();

    int gid = blockIdx.x * PH_THREADS + threadIdx.x;   // GB*CHUNK threads
    int b = gid >> CHUNK_BITS;
    int u = gid & (CHUNK - 1);
    __half2* p = buf + (long)b * DIM + u;

    __half2 hh[32];
#pragma unroll
    for (int r = 0; r < 32; ++r) hh[r] = p[(long)r << CHUNK_BITS];

    float2 x[32];
#pragma unroll
    for (int r = 0; r < 32; ++r) x[r] = __half22float2(hh[r]);

#pragma unroll
    for (int w = 0; w < 5; ++w) {
        float4 g = sg[w];
        int m = 16 >> w;                     // wire w <-> r-bit (4-w)
#pragma unroll
        for (int r = 0; r < 32; ++r)
            if (!(r & m)) apply_gate(x[r], x[r | m], g);
    }

#pragma unroll
    for (int r = 0; r < 32; ++r) p[(long)r << CHUNK_BITS] = __float22half2_rn(x[r]);
}

// first variant: reads separate fp32 re/im arrays, writes half2
__global__ void __launch_bounds__(PH_THREADS, 2)
k_pass_high_first(const float* __restrict__ sre,
                  const float* __restrict__ sim,
                  __half2* __restrict__ out,
                  const float* __restrict__ params) {
    __shared__ float4 sg[5];
    load_gates(sg, params, 0, 0, 5, threadIdx.x);
    __syncthreads();

    int gid = blockIdx.x * PH_THREADS + threadIdx.x;
    int b = gid >> CHUNK_BITS;
    int u = gid & (CHUNK - 1);
    long base = (long)b * DIM + u;

    float2 x[32];
#pragma unroll
    for (int r = 0; r < 32; ++r) x[r].x = sre[base + ((long)r << CHUNK_BITS)];
#pragma unroll
    for (int r = 0; r < 32; ++r) x[r].y = sim[base + ((long)r << CHUNK_BITS)];

#pragma unroll
    for (int w = 0; w < 5; ++w) {
        float4 g = sg[w];
        int m = 16 >> w;
#pragma unroll
        for (int r = 0; r < 32; ++r)
            if (!(r & m)) apply_gate(x[r], x[r | m], g);
    }
    __half2* p = out + base;
#pragma unroll
    for (int r = 0; r < 32; ++r) p[(long)r << CHUNK_BITS] = __float22half2_rn(x[r]);
}

// ---------------------------------------------------------------------------
// pass_low: wires 5..17 (bits 12..0) in 64KB fp32 shared tiles (2 CTAs/SM);
// global state is half2; then the CNOT-ladder permutation (inverse-Gray
// scatter, 8B paired stores). last==true: compute <Z_w> partials instead.
// ---------------------------------------------------------------------------
__global__ void __launch_bounds__(PL_THREADS, 2)
k_pass_low(const __half2* __restrict__ in,
           __half2* __restrict__ out,
           const float* __restrict__ params,
           float* __restrict__ partial,
           int layer, int last) {
    extern __shared__ float2 sh[];           // 2^13 float2 = 64KB
    __shared__ float4 sg[13];                // wires 5..17 -> sg[w-5]
    int tid = threadIdx.x;
    load_gates(sg, params, layer, 5, 13, tid);

    int b = blockIdx.x >> 5;
    int H = blockIdx.x & 31;                 // source chunk (bits 13..17)
    const uint4* src = (const uint4*)(in + (long)b * DIM + ((long)H << CHUNK_BITS));

    // batched fill: 4 independent 16B loads (each = 4 half2) per thread
    {
        uint4 v[4];
#pragma unroll
        for (int k = 0; k < 4; ++k) v[k] = src[tid + k * PL_THREADS];
#pragma unroll
        for (int k = 0; k < 4; ++k) {
            int t = 4 * (tid + k * PL_THREADS);
            sh[SW(t)]     = bits2f2(v[k].x);
            sh[SW(t + 1)] = bits2f2(v[k].y);
            sh[SW(t + 2)] = bits2f2(v[k].z);
            sh[SW(t + 3)] = bits2f2(v[k].w);
        }
    }
    __syncthreads();

    // stage A: bits 0..3 (wires 17..14). 512 groups of 16, 1 per thread.
    {
        int base = tid << 4;
        float2 x[16];
#pragma unroll
        for (int j = 0; j < 16; ++j) x[j] = sh[SW(base + j)];
#pragma unroll
        for (int p = 0; p < 4; ++p) {
            float4 g = sg[12 - p];           // wire 17-p
            int m = 1 << p;
#pragma unroll
            for (int j = 0; j < 16; ++j)
                if (!(j & m)) apply_gate(x[j], x[j | m], g);
        }
#pragma unroll
        for (int j = 0; j < 16; ++j) sh[SW(base + j)] = x[j];
    }
    __syncthreads();

    // stage B: bits 4..7 (wires 13..10). group = bits 0..3 x bits 8..12.
    {
        int base = (tid & 15) | ((tid >> 4) << 8);
        float2 x[16];
#pragma unroll
        for (int j = 0; j < 16; ++j) x[j] = sh[SW(base | (j << 4))];
#pragma unroll
        for (int p = 0; p < 4; ++p) {
            float4 g = sg[8 - p];            // wire 13-p
            int m = 1 << p;
#pragma unroll
            for (int j = 0; j < 16; ++j)
                if (!(j & m)) apply_gate(x[j], x[j | m], g);
        }
#pragma unroll
        for (int j = 0; j < 16; ++j) sh[SW(base | (j << 4))] = x[j];
    }
    __syncthreads();

    // stage C: bits 8..11 (wires 9..6). group = bits 0..7 x bit 12.
    {
        int base = (tid & 255) | ((tid >> 8) << 12);
        float2 x[16];
#pragma unroll
        for (int j = 0; j < 16; ++j) x[j] = sh[SW(base | (j << 8))];
#pragma unroll
        for (int p = 0; p < 4; ++p) {
            float4 g = sg[4 - p];            // wire 9-p
            int m = 1 << p;
#pragma unroll
            for (int j = 0; j < 16; ++j)
                if (!(j & m)) apply_gate(x[j], x[j | m], g);
        }
#pragma unroll
        for (int j = 0; j < 16; ++j) sh[SW(base | (j << 8))] = x[j];
    }
    __syncthreads();

    // stage D: bit 12 (wire 5). 4096 pairs, 8 per thread.
    {
        float4 g = sg[0];                    // wire 5
#pragma unroll
        for (int j = 0; j < 8; ++j) {
            int lo = tid * 8 + j;
            float2 a = sh[SW(lo)];
            float2 bb = sh[SW(lo | 4096)];
            apply_gate(a, bb, g);
            sh[SW(lo)] = a;
            sh[SW(lo | 4096)] = bb;
        }
    }
    __syncthreads();

    // CNOT-ladder permutation: dest = invgray18(src)
    int pm = (__popc(H) & 1) ? (CHUNK - 1) : 0;
    int Hd = H ^ (H >> 1); Hd ^= Hd >> 2; Hd ^= Hd >> 4;  // invgray5

    if (!last) {
        // invgray maps pair {t,t+1} (t even) to {q, q^1}: 8B paired stores
        uint2* dst = (uint2*)(out + (long)b * DIM + ((long)Hd << CHUNK_BITS));
#pragma unroll
        for (int k = 0; k < 8; ++k) {
            int t = 2 * (tid + k * PL_THREADS);
            int q = invgray(t) ^ pm;
            unsigned b0 = f22bits(sh[SW(t)]);
            unsigned b1 = f22bits(sh[SW(t + 1)]);
            uint2 o;
            o.x = (q & 1) ? b1 : b0;
            o.y = (q & 1) ? b0 : b1;
            dst[q >> 1] = o;
        }
    } else {
        float acc[NUM_WIRES];
#pragma unroll
        for (int w = 0; w < NUM_WIRES; ++w) acc[w] = 0.0f;
        int hi = Hd << CHUNK_BITS;
#pragma unroll
        for (int k = 0; k < 8; ++k) {
            int t = 2 * (tid + k * PL_THREADS);
            float2 v0 = sh[SW(t)];
            float2 v1 = sh[SW(t + 1)];
            float pr0 = v0.x * v0.x + v0.y * v0.y;
            float pr1 = v1.x * v1.x + v1.y * v1.y;
            int q = invgray(t) ^ pm;
            int d = hi | q;
            float both = pr0 + pr1;
            unsigned bb = __float_as_uint(both);
#pragma unroll
            for (int w = 0; w < 17; ++w) {
                unsigned bit = (unsigned)(d >> (17 - w)) & 1u;
                acc[w] += __uint_as_float(bb ^ (bit << 31));
            }
            float diff = pr0 - pr1;
            acc[17] += (q & 1) ? -diff : diff;
        }
#pragma unroll
        for (int w = 0; w < NUM_WIRES; ++w)
#pragma unroll
            for (int o = 16; o; o >>= 1)
                acc[w] += __shfl_down_sync(0xFFFFFFFFu, acc[w], o);
        __syncthreads();
        float* scratch = (float*)sh;
        int warp = tid >> 5, lane = tid & 31;
        if (lane == 0)
#pragma unroll
            for (int w = 0; w < NUM_WIRES; ++w) scratch[warp * NUM_WIRES + w] = acc[w];
        __syncthreads();
        if (tid < NUM_WIRES) {
            float s = 0.0f;
#pragma unroll
            for (int k = 0; k < PL_THREADS / 32; ++k) s += scratch[k * NUM_WIRES + tid];
            partial[(b * NCHUNK + H) * NUM_WIRES + tid] = s;
        }
    }
}

// ---------------------------------------------------------------------------
// head: feats @ head_w.T + head_b
// ---------------------------------------------------------------------------
__global__ void k_head(const float* __restrict__ head_w,
                       const float* __restrict__ head_b,
                       float* __restrict__ out) {
    int b = threadIdx.x;
    if (b < BATCH) {
        float s = head_b[0];
#pragma unroll
        for (int w = 0; w < NUM_WIRES; ++w) {
            float f = 0.0f;
#pragma unroll
            for (int c = 0; c < NCHUNK; ++c)
                f += g_partial[(b * NCHUNK + c) * NUM_WIRES + w];
            s = fmaf(f, head_w[w], s);
        }
        out[b] = s;
    }
}

// ---------------------------------------------------------------------------
extern "C" void kernel_launch(void* const* d_in, const int* in_sizes, int n_in,
                              void* d_out, int out_size) {
    const float* state_re = (const float*)d_in[0];
    const float* state_im = (const float*)d_in[1];
    const float* params   = (const float*)d_in[2];
    const float* head_w   = (const float*)d_in[3];
    const float* head_b   = (const float*)d_in[4];
    float* out = (float*)d_out;

    cudaFuncSetAttribute(k_pass_low, cudaFuncAttributeMaxDynamicSharedMemorySize,
                         CHUNK * (int)sizeof(float2));

    static __half2* h0p = nullptr;
    static __half2* h1p = nullptr;
    static float*   ptp = nullptr;
    if (!h0p) {
        cudaGetSymbolAddress((void**)&h0p, g_h0);
        cudaGetSymbolAddress((void**)&h1p, g_h1);
        cudaGetSymbolAddress((void**)&ptp, g_partial);
    }

    const int ph_blocks = (GB * CHUNK) / PH_THREADS;   // 1024
    const int pl_blocks = GB * NCHUNK;                 // 1024
    const int shmem = CHUNK * (int)sizeof(float2);     // 64KB

    // Process batch in L2-resident groups of GB=32 (working set 67MB < L2)
    for (int grp = 0; grp < BATCH / GB; ++grp) {
        long boff = (long)grp * GB * DIM;
        __half2* h0 = h0p + boff;
        __half2* h1 = h1p + boff;
        float* part = ptp + (long)grp * GB * NCHUNK * NUM_WIRES;

        // layer 0
        k_pass_high_first<<<ph_blocks, PH_THREADS>>>(state_re + boff, state_im + boff, h0, params);
        k_pass_low<<<pl_blocks, PL_THREADS, shmem>>>(h0, h1, params, part, 0, 0);
        // layer 1
        k_pass_high<<<ph_blocks, PH_THREADS>>>(h1, params, 1);
        k_pass_low<<<pl_blocks, PL_THREADS, shmem>>>(h1, h0, params, part, 1, 0);
        // layer 2
        k_pass_high<<<ph_blocks, PH_THREADS>>>(h0, params, 2);
        k_pass_low<<<pl_blocks, PL_THREADS, shmem>>>(h0, h1, params, part, 2, 1);
    }

    k_head<<<1, 64>>>(head_w, head_b, out);
}